// round 16
// baseline (speedup 1.0000x reference)
#include <cuda_runtime.h>

#define BDIM 2048
#define TDIM 2048
#define FDIM 12
#define CHUNK 64
#define WARM  96
#define NBLK  256
#define NTHR  256
#define SCALE (-2.8853900817779268f)   /* -2/ln(2): exp(-2p) = 2^(SCALE*p) */

typedef unsigned long long ull_t;
// Packed f32x2 FMA (SASS FFMA2; PTX-only form). Two independent fma.rn.
__device__ __forceinline__ float2 ffma2(float2 a, float2 b, float2 c) {
    ull_t au = *(ull_t*)&a, bu = *(ull_t*)&b, cu = *(ull_t*)&c, du;
    asm("fma.rn.f32x2 %0, %1, %2, %3;" : "=l"(du) : "l"(au), "l"(bu), "l"(cu));
    return *(float2*)&du;
}

// Scratch (device globals: allocation-free per harness rules)
// Padded by 32 t-rows: phase-B lookahead reads past t=2047 without clamping.
__device__ __align__(16) float g_xi[(size_t)(TDIM + 32) * BDIM * 4];   // [t][b][4], pre-scaled + r-shifted
__device__ unsigned int g_bar;                                          // grid-barrier ticket

__global__ void __launch_bounds__(NTHR, 2) fused_kernel(
    const float* __restrict__ x, const float* __restrict__ embed,
    const float* __restrict__ W1, const float* __restrict__ b1,
    const float* __restrict__ W2, const float* __restrict__ b2,
    const float* __restrict__ Wi, const float* __restrict__ bi,
    const float* __restrict__ Wh, const float* __restrict__ W3,
    const float* __restrict__ b3, const float* __restrict__ W4,
    const float* __restrict__ b4, float* __restrict__ out)
{
    __shared__ float smem_buf[8 * 32 * 33];   // phase A: sxi transpose tile; phase B: per-warp sy tiles
    __shared__ float s_w1[64], s_b1[4];

    int s = threadIdx.x;
    if (s < 64) s_w1[s] = W1[s];
    if (s < 4)  s_b1[s] = b1[s];

    // Fused weights: W2i = (W2@Wi)*SCALE; b2i = (b2@Wi + bi)*SCALE - SUM_k Wh[k][d]*SCALE
    // (the Wh column-sum shift re-parameterizes the scan in r-space: h = 2r - 1).
    float w2i[16], b2i[4];
    {
        float wiv[16], w2v[16];
        #pragma unroll
        for (int q = 0; q < 16; q++) { wiv[q] = __ldg(Wi + q); w2v[q] = __ldg(W2 + q); }
        #pragma unroll
        for (int k = 0; k < 4; k++) {
            #pragma unroll
            for (int d = 0; d < 4; d++) {
                float acc = 0.f;
                #pragma unroll
                for (int m = 0; m < 4; m++) acc = fmaf(w2v[k * 4 + m], wiv[m * 4 + d], acc);
                w2i[k * 4 + d] = acc * SCALE;
            }
        }
        #pragma unroll
        for (int d = 0; d < 4; d++) {
            float acc = __ldg(bi + d);
            #pragma unroll
            for (int m = 0; m < 4; m++) acc = fmaf(__ldg(b2 + m), wiv[m * 4 + d], acc);
            float wsum = 0.f;
            #pragma unroll
            for (int k = 0; k < 4; k++) wsum += __ldg(Wh + k * 4 + d);
            b2i[d] = (acc - wsum) * SCALE;      // fold -SUM_k whs[k][d] into the bias
        }
    }
    float w1x[48];
    #pragma unroll
    for (int q = 0; q < 48; q++) w1x[q] = __ldg(W1 + q);
    __syncthreads();

    // ---------------- Phase A: g_xi[t][b] = SCALE*(relu(x@W1x + cb)@W2i) + b2i'  [R13]
    {
        float4* sxi = (float4*)smem_buf;            // [32][33]
        int bl = s >> 3, tl0 = s & 7;
        for (int tIdx = blockIdx.x; tIdx < 64 * 64; tIdx += NBLK) {
            int b0 = (tIdx & 63) * 32;
            int t0 = (tIdx >> 6) * 32;
            int b  = b0 + bl;
            float4 e4 = ((const float4*)embed)[b];
            float cb[4];
            #pragma unroll
            for (int d = 0; d < 4; d++) {
                float cc = s_b1[d];
                cc = fmaf(e4.x, s_w1[48 + d], cc);
                cc = fmaf(e4.y, s_w1[52 + d], cc);
                cc = fmaf(e4.z, s_w1[56 + d], cc);
                cc = fmaf(e4.w, s_w1[60 + d], cc);
                cb[d] = cc;
            }
            #pragma unroll
            for (int i = 0; i < 4; i++) {
                int tl = tl0 + 8 * i;
                const float4* xp4 = (const float4*)(x + ((size_t)b * TDIM + (size_t)(t0 + tl)) * FDIM);
                float4 xa = __ldcs(xp4 + 0), xb = __ldcs(xp4 + 1), xc = __ldcs(xp4 + 2);
                float xv[12] = {xa.x, xa.y, xa.z, xa.w, xb.x, xb.y, xb.z, xb.w, xc.x, xc.y, xc.z, xc.w};
                float u[4] = {cb[0], cb[1], cb[2], cb[3]};
                #pragma unroll
                for (int f = 0; f < 12; f++) {
                    #pragma unroll
                    for (int d = 0; d < 4; d++) u[d] = fmaf(xv[f], w1x[f * 4 + d], u[d]);
                }
                #pragma unroll
                for (int d = 0; d < 4; d++) u[d] = fmaxf(u[d], 0.f);
                float o[4] = {b2i[0], b2i[1], b2i[2], b2i[3]};
                #pragma unroll
                for (int k = 0; k < 4; k++) {
                    #pragma unroll
                    for (int d = 0; d < 4; d++) o[d] = fmaf(u[k], w2i[k * 4 + d], o[d]);
                }
                sxi[tl * 33 + bl] = make_float4(o[0], o[1], o[2], o[3]);
            }
            __syncthreads();
            int bl2 = s & 31, th = s >> 5;
            #pragma unroll
            for (int i = 0; i < 4; i++) {
                int tt = th + 8 * i;
                ((float4*)g_xi)[(size_t)(t0 + tt) * BDIM + (b0 + bl2)] = sxi[tt * 33 + bl2];
            }
            __syncthreads();
        }
    }

    // ---------------- Grid barrier (ticket-based; robust across graph replays)
    if (s == 0) {
        __threadfence();
        unsigned t = atomicAdd(&g_bar, 1u);
        unsigned target = (t / NBLK + 1u) * NBLK;
        while (*(volatile unsigned*)&g_bar < target) __nanosleep(64);
        __threadfence();
    }
    __syncthreads();

    // ---------------- Phase B: r-space scan + fused head (state r = (tanh+1)/2, init 0.5)
    {
        int wl = s >> 5, lane = s & 31;
        int sid = blockIdx.x * 8 + wl;            // 2048 scan warps
        {
            // r-space packed weights: 2x the h-space versions
            float2 whA[4], whB[4];                // q01 / q23 coefficient pairs per r_i
            #pragma unroll
            for (int k = 0; k < 4; k++) {
                whA[k] = make_float2(2.0f * __ldg(Wh + 4 * k)     * SCALE,
                                     2.0f * __ldg(Wh + 4 * k + 1) * SCALE);
                whB[k] = make_float2(2.0f * __ldg(Wh + 4 * k + 2) * SCALE,
                                     2.0f * __ldg(Wh + 4 * k + 3) * SCALE);
            }
            // head in r-space: z_j = (b3_j - SUM_i W3[i][j]) + SUM_i (2*W3[i][j]) r_i
            float2 w3p[3][4], b3p[3];
            #pragma unroll
            for (int p = 0; p < 3; p++) {
                float s0 = 0.f, s1 = 0.f;
                #pragma unroll
                for (int i = 0; i < 4; i++) { s0 += __ldg(W3 + i * 6 + 2 * p); s1 += __ldg(W3 + i * 6 + 2 * p + 1); }
                b3p[p] = make_float2(__ldg(b3 + 2 * p) - s0, __ldg(b3 + 2 * p + 1) - s1);
                #pragma unroll
                for (int i = 0; i < 4; i++)
                    w3p[p][i] = make_float2(2.0f * __ldg(W3 + i * 6 + 2 * p),
                                            2.0f * __ldg(W3 + i * 6 + 2 * p + 1));
            }
            float w4v[6];
            #pragma unroll
            for (int q = 0; q < 6; q++) w4v[q] = __ldg(W4 + q);
            float b4v = __ldg(b4);

            int bw = sid & 63, c = sid >> 6;      // 64 row-groups x 32 chunks
            int b  = bw * 32 + lane, b0 = bw * 32;

            int base, nTiles, warmTiles;
            if (c == 0)      { base = 0;                 nTiles = 2; warmTiles = 0; }
            else if (c == 1) { base = 0;                 nTiles = 4; warmTiles = 2; }
            else             { base = c * CHUNK - WARM;  nTiles = 5; warmTiles = 3; }

            float* sy = smem_buf + wl * 32 * 33;  // per-warp [t][b] tile, pad 33
            const float4* xp = (const float4*)g_xi + b;   // lane-fixed column
            float2 rr0 = make_float2(0.5f, 0.5f), rr1 = rr0, rr2 = rr0, rr3 = rr0;  // r(h=0)=0.5

            const int U = 4;
            float4 bufA[U], bufB[U];
            #pragma unroll
            for (int u = 0; u < U; u++) bufA[u] = xp[(size_t)(base + u) * BDIM];

// One r-space scan step: q = v' + SUM 2whs*r; e = 2^q; r = rcp(1+e) via paired rcp.
// No h-forming instructions; rcp output feeds the next q directly.
#define PSTEP(v)                                                                         \
    {                                                                                    \
        float2 v01 = make_float2(v.x, v.y), v23 = make_float2(v.z, v.w);                 \
        float2 q01 = ffma2(rr0, whA[0], v01);                                            \
        q01 = ffma2(rr1, whA[1], q01);                                                   \
        q01 = ffma2(rr2, whA[2], q01);                                                   \
        q01 = ffma2(rr3, whA[3], q01);                                                   \
        float2 q23 = ffma2(rr0, whB[0], v23);                                            \
        q23 = ffma2(rr1, whB[1], q23);                                                   \
        q23 = ffma2(rr2, whB[2], q23);                                                   \
        q23 = ffma2(rr3, whB[3], q23);                                                   \
        float e0, e1, e2, e3, rp01, rp23;                                                \
        asm("ex2.approx.f32 %0, %1;" : "=f"(e0) : "f"(q01.x));                           \
        asm("ex2.approx.f32 %0, %1;" : "=f"(e1) : "f"(q01.y));                           \
        asm("ex2.approx.f32 %0, %1;" : "=f"(e2) : "f"(q23.x));                           \
        asm("ex2.approx.f32 %0, %1;" : "=f"(e3) : "f"(q23.y));                           \
        float t0 = e0 + 1.0f, t1 = e1 + 1.0f, t2 = e2 + 1.0f, t3 = e3 + 1.0f;            \
        asm("rcp.approx.f32 %0, %1;" : "=f"(rp01) : "f"(t0 * t1));                       \
        asm("rcp.approx.f32 %0, %1;" : "=f"(rp23) : "f"(t2 * t3));                       \
        float r0 = rp01 * t1, r1 = rp01 * t0, r2 = rp23 * t3, r3 = rp23 * t2;            \
        rr0 = make_float2(r0, r0); rr1 = make_float2(r1, r1);                            \
        rr2 = make_float2(r2, r2); rr3 = make_float2(r3, r3);                            \
    }

// Packed output head from rr0..rr3 into sy slot.
#define PHEAD(slot)                                                                      \
    {                                                                                    \
        float2 z01 = ffma2(rr0, w3p[0][0], b3p[0]);                                      \
        z01 = ffma2(rr1, w3p[0][1], z01);                                                \
        z01 = ffma2(rr2, w3p[0][2], z01);                                                \
        z01 = ffma2(rr3, w3p[0][3], z01);                                                \
        float2 z23 = ffma2(rr0, w3p[1][0], b3p[1]);                                      \
        z23 = ffma2(rr1, w3p[1][1], z23);                                                \
        z23 = ffma2(rr2, w3p[1][2], z23);                                                \
        z23 = ffma2(rr3, w3p[1][3], z23);                                                \
        float2 z45 = ffma2(rr0, w3p[2][0], b3p[2]);                                      \
        z45 = ffma2(rr1, w3p[2][1], z45);                                                \
        z45 = ffma2(rr2, w3p[2][2], z45);                                                \
        z45 = ffma2(rr3, w3p[2][3], z45);                                                \
        float y = b4v;                                                                   \
        y = fmaf(fmaxf(z01.x, 0.f), w4v[0], y);                                          \
        y = fmaf(fmaxf(z01.y, 0.f), w4v[1], y);                                          \
        y = fmaf(fmaxf(z23.x, 0.f), w4v[2], y);                                          \
        y = fmaf(fmaxf(z23.y, 0.f), w4v[3], y);                                          \
        y = fmaf(fmaxf(z45.x, 0.f), w4v[4], y);                                          \
        y = fmaf(fmaxf(z45.y, 0.f), w4v[5], y);                                          \
        sy[(slot) * 33 + lane] = y;                                                      \
    }

            int tb = 0;
            for (int tile = 0; tile < nTiles; ++tile) {
                bool doStore = (tile >= warmTiles);
                #pragma unroll
                for (int oct = 0; oct < 4; ++oct) {       // 4 x 8 steps = 32-step tile
                    #pragma unroll
                    for (int u = 0; u < U; u++)
                        bufB[u] = xp[(size_t)(base + tb + U + u) * BDIM];
                    #pragma unroll
                    for (int u = 0; u < U; u++) {
                        float4 v = bufA[u];
                        PSTEP(v)
                        if (doStore) PHEAD((tb + u) & 31)
                    }
                    #pragma unroll
                    for (int u = 0; u < U; u++)
                        bufA[u] = xp[(size_t)(base + tb + 2 * U + u) * BDIM];
                    #pragma unroll
                    for (int u = 0; u < U; u++) {
                        float4 v = bufB[u];
                        PSTEP(v)
                        if (doStore) PHEAD((tb + U + u) & 31)
                    }
                    tb += 2 * U;
                }
                if (doStore) {
                    __syncwarp();
                    int tileT = base + tile * 32;
                    #pragma unroll 8
                    for (int j = 0; j < 32; j++) {
                        __stcs(&out[(size_t)(b0 + j) * TDIM + tileT + lane], sy[lane * 33 + j]);
                    }
                    __syncwarp();
                }
            }
#undef PSTEP
#undef PHEAD
        }
    }
}

// ---------------------------------------------------------------- launch
extern "C" void kernel_launch(void* const* d_in, const int* in_sizes, int n_in,
                              void* d_out, int out_size) {
    const float* x     = (const float*)d_in[0];
    const float* embed = (const float*)d_in[1];
    const float* W1    = (const float*)d_in[2];
    const float* b1    = (const float*)d_in[3];
    const float* W2    = (const float*)d_in[4];
    const float* b2    = (const float*)d_in[5];
    const float* Wi    = (const float*)d_in[6];
    const float* bi    = (const float*)d_in[7];
    const float* Wh    = (const float*)d_in[8];
    const float* W3    = (const float*)d_in[9];
    const float* b3    = (const float*)d_in[10];
    const float* W4    = (const float*)d_in[11];
    const float* b4    = (const float*)d_in[12];
    float* out = (float*)d_out;

    fused_kernel<<<NBLK, NTHR>>>(x, embed, W1, b1, W2, b2, Wi, bi, Wh, W3, b3, W4, b4, out);
}

// round 17
// speedup vs baseline: 1.0692x; 1.0692x over previous
#include <cuda_runtime.h>

#define BDIM 2048
#define TDIM 2048
#define FDIM 12
#define CHUNK 64
#define WARM  80
#define NBLK  256
#define NTHR  256
#define SCALE (-2.8853900817779268f)   /* -2/ln(2): exp(-2p) = 2^(SCALE*p) */

// Scratch (device globals: allocation-free per harness rules)
// Padded by 64 t-rows: phase-B lookahead reads past t=2047 without clamping.
__device__ __align__(16) float g_xi[(size_t)(TDIM + 64) * BDIM * 4];   // [t][b][4], pre-scaled
__device__ unsigned int g_bar;                                          // grid-barrier ticket

__global__ void __launch_bounds__(NTHR, 2) fused_kernel(
    const float* __restrict__ x, const float* __restrict__ embed,
    const float* __restrict__ W1, const float* __restrict__ b1,
    const float* __restrict__ W2, const float* __restrict__ b2,
    const float* __restrict__ Wi, const float* __restrict__ bi,
    const float* __restrict__ Wh, const float* __restrict__ W3,
    const float* __restrict__ b3, const float* __restrict__ W4,
    const float* __restrict__ b4, float* __restrict__ out)
{
    __shared__ float smem_buf[8 * 32 * 33];   // phase A: sxi transpose tile; phase B: per-warp sy tiles
    __shared__ float s_w1[64], s_b1[4];

    int s = threadIdx.x;
    if (s < 64) s_w1[s] = W1[s];
    if (s < 4)  s_b1[s] = b1[s];

    // Per-thread fused weights: W2i = (W2@Wi)*SCALE, b2i = (b2@Wi + bi)*SCALE
    float w2i[16], b2i[4];
    {
        float wiv[16], w2v[16];
        #pragma unroll
        for (int q = 0; q < 16; q++) { wiv[q] = __ldg(Wi + q); w2v[q] = __ldg(W2 + q); }
        #pragma unroll
        for (int k = 0; k < 4; k++) {
            #pragma unroll
            for (int d = 0; d < 4; d++) {
                float acc = 0.f;
                #pragma unroll
                for (int m = 0; m < 4; m++) acc = fmaf(w2v[k * 4 + m], wiv[m * 4 + d], acc);
                w2i[k * 4 + d] = acc * SCALE;
            }
        }
        #pragma unroll
        for (int d = 0; d < 4; d++) {
            float acc = __ldg(bi + d);
            #pragma unroll
            for (int m = 0; m < 4; m++) acc = fmaf(__ldg(b2 + m), wiv[m * 4 + d], acc);
            b2i[d] = acc * SCALE;
        }
    }
    float w1x[48];
    #pragma unroll
    for (int q = 0; q < 48; q++) w1x[q] = __ldg(W1 + q);
    __syncthreads();

    // ---------------- Phase A: g_xi[t][b] = SCALE*(relu(x@W1x + cb)@W2i + b2i)  [R13]
    {
        float4* sxi = (float4*)smem_buf;            // [32][33]
        int bl = s >> 3, tl0 = s & 7;
        for (int tIdx = blockIdx.x; tIdx < 64 * 64; tIdx += NBLK) {
            int b0 = (tIdx & 63) * 32;
            int t0 = (tIdx >> 6) * 32;
            int b  = b0 + bl;
            float4 e4 = ((const float4*)embed)[b];
            float cb[4];
            #pragma unroll
            for (int d = 0; d < 4; d++) {
                float cc = s_b1[d];
                cc = fmaf(e4.x, s_w1[48 + d], cc);
                cc = fmaf(e4.y, s_w1[52 + d], cc);
                cc = fmaf(e4.z, s_w1[56 + d], cc);
                cc = fmaf(e4.w, s_w1[60 + d], cc);
                cb[d] = cc;
            }
            #pragma unroll
            for (int i = 0; i < 4; i++) {
                int tl = tl0 + 8 * i;
                const float4* xp4 = (const float4*)(x + ((size_t)b * TDIM + (size_t)(t0 + tl)) * FDIM);
                float4 xa = __ldcs(xp4 + 0), xb = __ldcs(xp4 + 1), xc = __ldcs(xp4 + 2);
                float xv[12] = {xa.x, xa.y, xa.z, xa.w, xb.x, xb.y, xb.z, xb.w, xc.x, xc.y, xc.z, xc.w};
                float u[4] = {cb[0], cb[1], cb[2], cb[3]};
                #pragma unroll
                for (int f = 0; f < 12; f++) {
                    #pragma unroll
                    for (int d = 0; d < 4; d++) u[d] = fmaf(xv[f], w1x[f * 4 + d], u[d]);
                }
                #pragma unroll
                for (int d = 0; d < 4; d++) u[d] = fmaxf(u[d], 0.f);
                float o[4] = {b2i[0], b2i[1], b2i[2], b2i[3]};
                #pragma unroll
                for (int k = 0; k < 4; k++) {
                    #pragma unroll
                    for (int d = 0; d < 4; d++) o[d] = fmaf(u[k], w2i[k * 4 + d], o[d]);
                }
                sxi[tl * 33 + bl] = make_float4(o[0], o[1], o[2], o[3]);
            }
            __syncthreads();
            int bl2 = s & 31, th = s >> 5;
            #pragma unroll
            for (int i = 0; i < 4; i++) {
                int tt = th + 8 * i;
                ((float4*)g_xi)[(size_t)(t0 + tt) * BDIM + (b0 + bl2)] = sxi[tt * 33 + bl2];
            }
            __syncthreads();
        }
    }

    // ---------------- Grid barrier (ticket-based; robust across graph replays)
    if (s == 0) {
        __threadfence();
        unsigned t = atomicAdd(&g_bar, 1u);
        unsigned target = (t / NBLK + 1u) * NBLK;
        while (*(volatile unsigned*)&g_bar < target) __nanosleep(64);
        __threadfence();
    }
    __syncthreads();

    // ---------------- Phase B: chunked scan (WARM=80, 16-step half-tiles) + fused head
    // Chunks 0-1 warm from t=0 (exact); c>=2 warm 80 steps from h=0 (rho^80 ~ 9e-5).
    {
        int wl = s >> 5, lane = s & 31;
        int sid = blockIdx.x * 8 + wl;            // 2048 scan warps
        {
            float whs[16];
            #pragma unroll
            for (int q = 0; q < 16; q++) whs[q] = __ldg(Wh + q) * SCALE;
            float w3[24];
            #pragma unroll
            for (int q = 0; q < 24; q++) w3[q] = __ldg(W3 + q);
            float b3v[6], w4v[6];
            #pragma unroll
            for (int q = 0; q < 6; q++) { b3v[q] = __ldg(b3 + q); w4v[q] = __ldg(W4 + q); }
            float b4v = __ldg(b4);

            int bw = sid & 63, c = sid >> 6;      // 64 row-groups x 32 chunks
            int b  = bw * 32 + lane, b0 = bw * 32;

            int base, nHalf, warmHalf;
            if (c == 0)      { base = 0;                nHalf = 4; warmHalf = 0; }   // 64 steps, exact
            else if (c == 1) { base = 0;                nHalf = 8; warmHalf = 4; }   // warm from t=0, exact
            else             { base = c * CHUNK - WARM; nHalf = 9; warmHalf = 5; }   // 80 warm + 64 store
            int warmSteps = warmHalf * 16;

            float* sy = smem_buf + wl * 32 * 33;  // per-warp [t][b] tile, pad 33
            const float4* xp = (const float4*)g_xi + b;   // lane-fixed column
            float h0 = 0.f, h1 = 0.f, h2 = 0.f, h3 = 0.f;

            const int U = 4;
            float4 bufA[U], bufB[U];
            #pragma unroll
            for (int u = 0; u < U; u++) bufA[u] = xp[(size_t)(base + u) * BDIM];

            int tb = 0, stored = 0;
            for (int half = 0; half < nHalf; ++half) {
                bool doStore = (half >= warmHalf);
                int sbase = stored & 31;              // 0 or 16
                #pragma unroll
                for (int rnd = 0; rnd < 2; ++rnd) {   // 2 x 8 steps = 16-step half-tile
                    // prefetch next U into B, compute from A
                    #pragma unroll
                    for (int u = 0; u < U; u++)
                        bufB[u] = xp[(size_t)(base + tb + U + u) * BDIM];
                    #pragma unroll
                    for (int u = 0; u < U; u++) {
                        float4 v = bufA[u];
                        float q0 = v.x + h0 * whs[0] + h1 * whs[4] + h2 * whs[8]  + h3 * whs[12];
                        float q1 = v.y + h0 * whs[1] + h1 * whs[5] + h2 * whs[9]  + h3 * whs[13];
                        float q2 = v.z + h0 * whs[2] + h1 * whs[6] + h2 * whs[10] + h3 * whs[14];
                        float q3 = v.w + h0 * whs[3] + h1 * whs[7] + h2 * whs[11] + h3 * whs[15];
                        float e0, e1, e2, e3, r0, r1, r2, r3;
                        asm("ex2.approx.f32 %0, %1;" : "=f"(e0) : "f"(q0));
                        asm("ex2.approx.f32 %0, %1;" : "=f"(e1) : "f"(q1));
                        asm("ex2.approx.f32 %0, %1;" : "=f"(e2) : "f"(q2));
                        asm("ex2.approx.f32 %0, %1;" : "=f"(e3) : "f"(q3));
                        asm("rcp.approx.f32 %0, %1;" : "=f"(r0) : "f"(e0 + 1.0f));
                        asm("rcp.approx.f32 %0, %1;" : "=f"(r1) : "f"(e1 + 1.0f));
                        asm("rcp.approx.f32 %0, %1;" : "=f"(r2) : "f"(e2 + 1.0f));
                        asm("rcp.approx.f32 %0, %1;" : "=f"(r3) : "f"(e3 + 1.0f));
                        h0 = fmaf(2.0f, r0, -1.0f); h1 = fmaf(2.0f, r1, -1.0f);
                        h2 = fmaf(2.0f, r2, -1.0f); h3 = fmaf(2.0f, r3, -1.0f);
                        if (doStore) {
                            float y = b4v;
                            #pragma unroll
                            for (int j = 0; j < 6; j++) {
                                float z = b3v[j];
                                z = fmaf(h0, w3[j],      z);
                                z = fmaf(h1, w3[6 + j],  z);
                                z = fmaf(h2, w3[12 + j], z);
                                z = fmaf(h3, w3[18 + j], z);
                                z = fmaxf(z, 0.f);
                                y = fmaf(z, w4v[j], y);
                            }
                            sy[(sbase + rnd * 8 + u) * 33 + lane] = y;
                        }
                    }
                    // prefetch next U into A, compute from B
                    #pragma unroll
                    for (int u = 0; u < U; u++)
                        bufA[u] = xp[(size_t)(base + tb + 2 * U + u) * BDIM];
                    #pragma unroll
                    for (int u = 0; u < U; u++) {
                        float4 v = bufB[u];
                        float q0 = v.x + h0 * whs[0] + h1 * whs[4] + h2 * whs[8]  + h3 * whs[12];
                        float q1 = v.y + h0 * whs[1] + h1 * whs[5] + h2 * whs[9]  + h3 * whs[13];
                        float q2 = v.z + h0 * whs[2] + h1 * whs[6] + h2 * whs[10] + h3 * whs[14];
                        float q3 = v.w + h0 * whs[3] + h1 * whs[7] + h2 * whs[11] + h3 * whs[15];
                        float e0, e1, e2, e3, r0, r1, r2, r3;
                        asm("ex2.approx.f32 %0, %1;" : "=f"(e0) : "f"(q0));
                        asm("ex2.approx.f32 %0, %1;" : "=f"(e1) : "f"(q1));
                        asm("ex2.approx.f32 %0, %1;" : "=f"(e2) : "f"(q2));
                        asm("ex2.approx.f32 %0, %1;" : "=f"(e3) : "f"(q3));
                        asm("rcp.approx.f32 %0, %1;" : "=f"(r0) : "f"(e0 + 1.0f));
                        asm("rcp.approx.f32 %0, %1;" : "=f"(r1) : "f"(e1 + 1.0f));
                        asm("rcp.approx.f32 %0, %1;" : "=f"(r2) : "f"(e2 + 1.0f));
                        asm("rcp.approx.f32 %0, %1;" : "=f"(r3) : "f"(e3 + 1.0f));
                        h0 = fmaf(2.0f, r0, -1.0f); h1 = fmaf(2.0f, r1, -1.0f);
                        h2 = fmaf(2.0f, r2, -1.0f); h3 = fmaf(2.0f, r3, -1.0f);
                        if (doStore) {
                            float y = b4v;
                            #pragma unroll
                            for (int j = 0; j < 6; j++) {
                                float z = b3v[j];
                                z = fmaf(h0, w3[j],      z);
                                z = fmaf(h1, w3[6 + j],  z);
                                z = fmaf(h2, w3[12 + j], z);
                                z = fmaf(h3, w3[18 + j], z);
                                z = fmaxf(z, 0.f);
                                y = fmaf(z, w4v[j], y);
                            }
                            sy[(sbase + rnd * 8 + 4 + u) * 33 + lane] = y;
                        }
                    }
                    tb += 2 * U;
                }
                if (doStore) {
                    stored += 16;
                    if ((stored & 31) == 0) {             // flush 32 stored steps
                        __syncwarp();
                        int tileT = base + warmSteps + stored - 32;
                        #pragma unroll 8
                        for (int j = 0; j < 32; j++) {
                            __stcs(&out[(size_t)(b0 + j) * TDIM + tileT + lane], sy[lane * 33 + j]);
                        }
                        __syncwarp();
                    }
                }
            }
        }
    }
}

// ---------------------------------------------------------------- launch
extern "C" void kernel_launch(void* const* d_in, const int* in_sizes, int n_in,
                              void* d_out, int out_size) {
    const float* x     = (const float*)d_in[0];
    const float* embed = (const float*)d_in[1];
    const float* W1    = (const float*)d_in[2];
    const float* b1    = (const float*)d_in[3];
    const float* W2    = (const float*)d_in[4];
    const float* b2    = (const float*)d_in[5];
    const float* Wi    = (const float*)d_in[6];
    const float* bi    = (const float*)d_in[7];
    const float* Wh    = (const float*)d_in[8];
    const float* W3    = (const float*)d_in[9];
    const float* b3    = (const float*)d_in[10];
    const float* W4    = (const float*)d_in[11];
    const float* b4    = (const float*)d_in[12];
    float* out = (float*)d_out;

    fused_kernel<<<NBLK, NTHR>>>(x, embed, W1, b1, W2, b2, Wi, bi, Wh, W3, b3, W4, b4, out);
}